// round 3
// baseline (speedup 1.0000x reference)
#include <cuda_runtime.h>
#include <cuda_fp16.h>
#include <cstddef>

// Problem dims (fixed by setup_inputs)
#define BB   256   // batch
#define PP   256   // pixels
#define ENCD 256   // encoder dim
#define DECD 512   // decoder dim
#define EE   256   // embedding dim
#define VV   5000  // vocab
#define TT   96    // timesteps
#define GG   2048  // 4*DEC gates

// ---------------- device scratch (no allocations allowed) ----------------
__device__ float  g_mean[BB * ENCD];
__device__ __half g_att1[(size_t)BB * PP * DECD];   // 67 MB (fp16)
__device__ __half g_encb[(size_t)BB * PP * ENCD];   // 33.5 MB (fp16)
__device__ float  g_embW[(size_t)VV * GG];          // 41 MB: embedding_w @ lstm_wih[:256]
__device__ float  g_h[2 * BB * DECD];
__device__ float  g_c[2 * BB * DECD];
__device__ float  g_att2[BB * DECD];
__device__ float  g_gate[BB * ENCD];
__device__ float  g_xg[BB * ENCD];                  // gate * awe
__device__ float  g_gates[BB * GG];

__device__ __forceinline__ float sigmoidf(float x) { return 1.f / (1.f + expf(-x)); }
__device__ __forceinline__ void store_out(float* p, float v) { *p = v; }
__device__ __forceinline__ void store_out(__half* p, float v) { *p = __float2half(v); }

// ---------------- generic tiled fp32 GEMM: C = act(A[M,K] @ W[K,N] + bias) ----------------
template<int BM, int BN, int BK, int TM, int TN, bool SIG, typename OutT>
__global__ __launch_bounds__((BM / TM) * (BN / TN))
void gemm_k(const float* __restrict__ A, const float* __restrict__ W,
            const float* __restrict__ bias, OutT* __restrict__ C,
            int M, int N, int K)
{
    constexpr int NT = (BM / TM) * (BN / TN);
    __shared__ float As[BK][BM];
    __shared__ float Ws[BK][BN];
    const int tid = threadIdx.x;
    const int tx = tid % (BN / TN);
    const int ty = tid / (BN / TN);
    const int m0 = blockIdx.y * BM, n0 = blockIdx.x * BN;

    float acc[TM][TN];
#pragma unroll
    for (int i = 0; i < TM; i++)
#pragma unroll
        for (int j = 0; j < TN; j++) acc[i][j] = 0.f;

    for (int k0 = 0; k0 < K; k0 += BK) {
#pragma unroll
        for (int i = tid; i < BM * BK; i += NT) {
            int r = i / BK, kk = i % BK;
            int m = m0 + r;
            As[kk][r] = (m < M) ? A[(size_t)m * K + k0 + kk] : 0.f;
        }
#pragma unroll
        for (int i = tid; i < BK * BN; i += NT) {
            int kk = i / BN, c = i % BN;
            int n = n0 + c;
            Ws[kk][c] = (n < N) ? W[(size_t)(k0 + kk) * N + n] : 0.f;
        }
        __syncthreads();
#pragma unroll
        for (int kk = 0; kk < BK; kk++) {
            float a[TM], w[TN];
#pragma unroll
            for (int i = 0; i < TM; i++) a[i] = As[kk][ty * TM + i];
#pragma unroll
            for (int j = 0; j < TN; j++) w[j] = Ws[kk][tx * TN + j];
#pragma unroll
            for (int i = 0; i < TM; i++)
#pragma unroll
                for (int j = 0; j < TN; j++) acc[i][j] += a[i] * w[j];
        }
        __syncthreads();
    }
#pragma unroll
    for (int i = 0; i < TM; i++) {
        int m = m0 + ty * TM + i;
        if (m >= M) continue;
#pragma unroll
        for (int j = 0; j < TN; j++) {
            int n = n0 + tx * TN + j;
            if (n >= N) continue;
            float v = acc[i][j] + (bias ? bias[n] : 0.f);
            if (SIG) v = sigmoidf(v);
            store_out(&C[(size_t)m * N + n], v);
        }
    }
}

// ---------------- one-time small kernels ----------------
__global__ void conv_k(const float* __restrict__ enc)
{
    size_t i = (size_t)blockIdx.x * blockDim.x + threadIdx.x;
    g_encb[i] = __float2half(enc[i]);
}

__global__ void mean_k(const float* __restrict__ enc)
{
    int b = blockIdx.x, e = threadIdx.x;
    const float* p = enc + (size_t)b * PP * ENCD + e;
    float s = 0.f;
#pragma unroll 8
    for (int pp = 0; pp < PP; pp++) s += p[(size_t)pp * ENCD];
    g_mean[b * ENCD + e] = s * (1.f / PP);
}

__global__ void lens_k(const int* __restrict__ lens, float* __restrict__ o)
{
    o[threadIdx.x] = (float)lens[threadIdx.x];
}

// ---------------- per-step: fused attention (e -> softmax -> awe -> gated x) ----------------
__global__ __launch_bounds__(256)
void attention_k(const float* __restrict__ wfull, const int* __restrict__ lens,
                 int t, float* __restrict__ alphas_out)
{
    __shared__ float att2s[DECD];
    __shared__ float wf[DECD];
    __shared__ float es[PP];
    __shared__ float red[32];
    int b = blockIdx.x, tid = threadIdx.x;
    att2s[tid]       = g_att2[b * DECD + tid];
    att2s[tid + 256] = g_att2[b * DECD + 256 + tid];
    wf[tid]       = wfull[tid];
    wf[tid + 256] = wfull[tid + 256];
    __syncthreads();

    int warp = tid >> 5, lane = tid & 31;
    const __half2* a1 = reinterpret_cast<const __half2*>(g_att1 + (size_t)b * PP * DECD);
    for (int p = warp; p < PP; p += 8) {
        const __half2* row = a1 + (size_t)p * (DECD / 2);
        float acc = 0.f;
#pragma unroll
        for (int i = 0; i < DECD / 64; i++) {
            int d2 = lane + 32 * i;
            float2 v = __half22float2(row[d2]);
            float x0 = v.x + att2s[2 * d2];
            float x1 = v.y + att2s[2 * d2 + 1];
            acc += fmaxf(x0, 0.f) * wf[2 * d2] + fmaxf(x1, 0.f) * wf[2 * d2 + 1];
        }
#pragma unroll
        for (int o = 16; o > 0; o >>= 1) acc += __shfl_xor_sync(0xffffffffu, acc, o);
        if (lane == 0) es[p] = acc;
    }
    __syncthreads();

    // softmax over 256
    float e = es[tid];
    float m = e;
#pragma unroll
    for (int o = 16; o > 0; o >>= 1) m = fmaxf(m, __shfl_xor_sync(0xffffffffu, m, o));
    if (lane == 0) red[warp] = m;
    __syncthreads();
    if (tid == 0) {
        float mm = red[0];
        for (int w = 1; w < 8; w++) mm = fmaxf(mm, red[w]);
        red[16] = mm;
    }
    __syncthreads();
    float ex = expf(e - red[16]);
    float s = ex;
#pragma unroll
    for (int o = 16; o > 0; o >>= 1) s += __shfl_xor_sync(0xffffffffu, s, o);
    if (lane == 0) red[warp] = s;
    __syncthreads();
    if (tid == 0) {
        float ss = 0.f;
        for (int w = 0; w < 8; w++) ss += red[w];
        red[17] = ss;
    }
    __syncthreads();
    float alpha = ex / red[17];
    es[tid] = alpha;
    int active = lens[b] > t;
    alphas_out[((size_t)b * TT + t) * PP + tid] = active ? alpha : 0.f;
    __syncthreads();

    // awe[e'] = sum_p alpha[p] * enc[b,p,e'];  xg = gate * awe
    const __half* eb = g_encb + (size_t)b * PP * ENCD;
    float acc = 0.f;
#pragma unroll 8
    for (int p = 0; p < PP; p++) acc += es[p] * __half2float(eb[(size_t)p * ENCD + tid]);
    g_xg[b * ENCD + tid] = g_gate[b * ENCD + tid] * acc;
}

// ---------------- per-step: LSTM preactivations ----------------
// gates = embW[cap[b,t]] + xg @ wih[256:512] + h @ whh + bih + bhh
__global__ __launch_bounds__(256)
void gates_k(const float* __restrict__ h, const float* __restrict__ wih_bot,
             const float* __restrict__ whh, const float* __restrict__ bih,
             const float* __restrict__ bhh, const int* __restrict__ caps, int t)
{
    constexpr int BM = 64, BN = 64, BK = 16, TM = 4, TN = 4, NT = 256;
    __shared__ float As[BK][BM];
    __shared__ float Ws[BK][BN];
    int tid = threadIdx.x, tx = tid % 16, ty = tid / 16;
    int m0 = blockIdx.y * BM, n0 = blockIdx.x * BN;
    float acc[TM][TN];
#pragma unroll
    for (int i = 0; i < TM; i++)
#pragma unroll
        for (int j = 0; j < TN; j++) acc[i][j] = 0.f;

    // pass 1: xg[BB,ENCD] @ wih_bot[ENCD,GG]
    for (int k0 = 0; k0 < ENCD; k0 += BK) {
#pragma unroll
        for (int i = tid; i < BM * BK; i += NT) {
            int r = i / BK, kk = i % BK;
            As[kk][r] = g_xg[(m0 + r) * ENCD + k0 + kk];
        }
#pragma unroll
        for (int i = tid; i < BK * BN; i += NT) {
            int kk = i / BN, c = i % BN;
            Ws[kk][c] = wih_bot[(size_t)(k0 + kk) * GG + n0 + c];
        }
        __syncthreads();
#pragma unroll
        for (int kk = 0; kk < BK; kk++) {
            float a[TM], w[TN];
#pragma unroll
            for (int i = 0; i < TM; i++) a[i] = As[kk][ty * TM + i];
#pragma unroll
            for (int j = 0; j < TN; j++) w[j] = Ws[kk][tx * TN + j];
#pragma unroll
            for (int i = 0; i < TM; i++)
#pragma unroll
                for (int j = 0; j < TN; j++) acc[i][j] += a[i] * w[j];
        }
        __syncthreads();
    }
    // pass 2: h[BB,DECD] @ whh[DECD,GG]
    for (int k0 = 0; k0 < DECD; k0 += BK) {
#pragma unroll
        for (int i = tid; i < BM * BK; i += NT) {
            int r = i / BK, kk = i % BK;
            As[kk][r] = h[(m0 + r) * DECD + k0 + kk];
        }
#pragma unroll
        for (int i = tid; i < BK * BN; i += NT) {
            int kk = i / BN, c = i % BN;
            Ws[kk][c] = whh[(size_t)(k0 + kk) * GG + n0 + c];
        }
        __syncthreads();
#pragma unroll
        for (int kk = 0; kk < BK; kk++) {
            float a[TM], w[TN];
#pragma unroll
            for (int i = 0; i < TM; i++) a[i] = As[kk][ty * TM + i];
#pragma unroll
            for (int j = 0; j < TN; j++) w[j] = Ws[kk][tx * TN + j];
#pragma unroll
            for (int i = 0; i < TM; i++)
#pragma unroll
                for (int j = 0; j < TN; j++) acc[i][j] += a[i] * w[j];
        }
        __syncthreads();
    }
#pragma unroll
    for (int i = 0; i < TM; i++) {
        int m = m0 + ty * TM + i;
        int idx = caps[m * TT + t];
        const float* er = g_embW + (size_t)idx * GG + n0 + tx * TN;
        size_t base = (size_t)m * GG + n0 + tx * TN;
#pragma unroll
        for (int j = 0; j < TN; j++) {
            int n = n0 + tx * TN + j;
            g_gates[base + j] = acc[i][j] + er[j] + bih[n] + bhh[n];
        }
    }
}

// ---------------- per-step: LSTM cell pointwise ----------------
__global__ void cell_k(const float* __restrict__ cold, float* __restrict__ cnew,
                       float* __restrict__ hnew)
{
    int b = blockIdx.x, d = threadIdx.x;
    const float* g = g_gates + (size_t)b * GG;
    float ig = sigmoidf(g[d]);
    float fg = sigmoidf(g[DECD + d]);
    float gg = tanhf(g[2 * DECD + d]);
    float og = sigmoidf(g[3 * DECD + d]);
    float c = fg * cold[b * DECD + d] + ig * gg;
    cnew[b * DECD + d] = c;
    hnew[b * DECD + d] = og * tanhf(c);
}

// ---------------- per-step: fc projection, masked by caption length ----------------
__global__ __launch_bounds__(256)
void fc_k(const float* __restrict__ h, const float* __restrict__ fcw,
          const float* __restrict__ fcb, const int* __restrict__ lens,
          int t, float* __restrict__ outp)
{
    constexpr int BM = 64, BN = 64, BK = 16, TM = 4, TN = 4, NT = 256;
    int m0 = blockIdx.y * BM, n0 = blockIdx.x * BN;
    if (lens[m0] <= t) return;  // lens sorted desc: whole row-block inactive
    __shared__ float As[BK][BM];
    __shared__ float Ws[BK][BN];
    int tid = threadIdx.x, tx = tid % 16, ty = tid / 16;
    float acc[TM][TN];
#pragma unroll
    for (int i = 0; i < TM; i++)
#pragma unroll
        for (int j = 0; j < TN; j++) acc[i][j] = 0.f;

    for (int k0 = 0; k0 < DECD; k0 += BK) {
#pragma unroll
        for (int i = tid; i < BM * BK; i += NT) {
            int r = i / BK, kk = i % BK;
            As[kk][r] = h[(m0 + r) * DECD + k0 + kk];
        }
#pragma unroll
        for (int i = tid; i < BK * BN; i += NT) {
            int kk = i / BN, c = i % BN;
            int n = n0 + c;
            Ws[kk][c] = (n < VV) ? fcw[(size_t)(k0 + kk) * VV + n] : 0.f;
        }
        __syncthreads();
#pragma unroll
        for (int kk = 0; kk < BK; kk++) {
            float a[TM], w[TN];
#pragma unroll
            for (int i = 0; i < TM; i++) a[i] = As[kk][ty * TM + i];
#pragma unroll
            for (int j = 0; j < TN; j++) w[j] = Ws[kk][tx * TN + j];
#pragma unroll
            for (int i = 0; i < TM; i++)
#pragma unroll
                for (int j = 0; j < TN; j++) acc[i][j] += a[i] * w[j];
        }
        __syncthreads();
    }
#pragma unroll
    for (int i = 0; i < TM; i++) {
        int m = m0 + ty * TM + i;
        if (lens[m] <= t) continue;
#pragma unroll
        for (int j = 0; j < TN; j++) {
            int n = n0 + tx * TN + j;
            if (n < VV)
                outp[((size_t)m * TT + t) * VV + n] = acc[i][j] + fcb[n];
        }
    }
}

// ---------------- host orchestration ----------------
extern "C" void kernel_launch(void* const* d_in, const int* in_sizes, int n_in,
                              void* d_out, int out_size)
{
    const float* enc        = (const float*)d_in[0];
    const int*   caps       = (const int*)d_in[1];
    const int*   lens       = (const int*)d_in[2];
    const float* embedding  = (const float*)d_in[3];
    const float* enc_att_w  = (const float*)d_in[4];
    const float* enc_att_b  = (const float*)d_in[5];
    const float* dec_att_w  = (const float*)d_in[6];
    const float* dec_att_b  = (const float*)d_in[7];
    const float* full_att_w = (const float*)d_in[8];
    // full_att_b (d_in[9]) is softmax-invariant; unused
    const float* lstm_wih   = (const float*)d_in[10];
    const float* lstm_whh   = (const float*)d_in[11];
    const float* lstm_bih   = (const float*)d_in[12];
    const float* lstm_bhh   = (const float*)d_in[13];
    const float* init_h_w   = (const float*)d_in[14];
    const float* init_h_b   = (const float*)d_in[15];
    const float* init_c_w   = (const float*)d_in[16];
    const float* init_c_b   = (const float*)d_in[17];
    const float* f_beta_w   = (const float*)d_in[18];
    const float* f_beta_b   = (const float*)d_in[19];
    const float* fc_w       = (const float*)d_in[20];
    const float* fc_b       = (const float*)d_in[21];

    float* out      = (float*)d_out;
    float* out_pred = out;                          // [B,T,V]
    float* out_lens = out + (size_t)BB * TT * VV;   // [B]
    float* out_alph = out_lens + BB;                // [B,T,P]

    cudaMemsetAsync(d_out, 0, (size_t)out_size * sizeof(float));

    float *p_mean, *p_h, *p_c, *p_att2, *p_gate, *p_embW;
    __half* p_att1;
    cudaGetSymbolAddress((void**)&p_mean, g_mean);
    cudaGetSymbolAddress((void**)&p_h, g_h);
    cudaGetSymbolAddress((void**)&p_c, g_c);
    cudaGetSymbolAddress((void**)&p_att2, g_att2);
    cudaGetSymbolAddress((void**)&p_gate, g_gate);
    cudaGetSymbolAddress((void**)&p_embW, g_embW);
    cudaGetSymbolAddress((void**)&p_att1, g_att1);

    // one-time precomputes
    conv_k<<<(BB * PP * ENCD) / 256, 256>>>(enc);
    mean_k<<<BB, 256>>>(enc);
    gemm_k<64, 64, 16, 4, 4, false, float>
        <<<dim3(DECD / 64, BB / 64), 256>>>(p_mean, init_h_w, init_h_b, p_h, BB, DECD, ENCD);
    gemm_k<64, 64, 16, 4, 4, false, float>
        <<<dim3(DECD / 64, BB / 64), 256>>>(p_mean, init_c_w, init_c_b, p_c, BB, DECD, ENCD);
    gemm_k<64, 64, 16, 4, 4, false, __half>
        <<<dim3(DECD / 64, (BB * PP) / 64), 256>>>(enc, enc_att_w, enc_att_b, p_att1,
                                                   BB * PP, DECD, ENCD);
    gemm_k<64, 64, 16, 4, 4, false, float>
        <<<dim3(GG / 64, (VV + 63) / 64), 256>>>(embedding, lstm_wih, nullptr, p_embW,
                                                 VV, GG, EE);

    for (int t = 0; t < TT; t++) {
        const float* hcur = p_h + (t & 1) * (BB * DECD);
        float*       hnext = p_h + ((t + 1) & 1) * (BB * DECD);
        const float* ccur = p_c + (t & 1) * (BB * DECD);
        float*       cnext = p_c + ((t + 1) & 1) * (BB * DECD);

        gemm_k<64, 32, 16, 4, 2, false, float>
            <<<dim3(DECD / 32, BB / 64), 256>>>(hcur, dec_att_w, dec_att_b, p_att2,
                                                BB, DECD, DECD);
        gemm_k<64, 32, 16, 4, 2, true, float>
            <<<dim3(ENCD / 32, BB / 64), 256>>>(hcur, f_beta_w, f_beta_b, p_gate,
                                                BB, ENCD, DECD);
        attention_k<<<BB, 256>>>(full_att_w, lens, t, out_alph);
        gates_k<<<dim3(GG / 64, BB / 64), 256>>>(hcur, lstm_wih + (size_t)EE * GG,
                                                 lstm_whh, lstm_bih, lstm_bhh, caps, t);
        cell_k<<<BB, DECD>>>(ccur, cnext, hnext);
        fc_k<<<dim3((VV + 63) / 64, BB / 64), 256>>>(hnext, fc_w, fc_b, lens, t, out_pred);
    }
    lens_k<<<1, BB>>>(lens, out_lens);
}

// round 4
// speedup vs baseline: 2.2119x; 2.2119x over previous
#include <cuda_runtime.h>
#include <cuda_fp16.h>
#include <cstddef>
#include <cstdint>

#define BB   256
#define PP   256
#define ENCD 256
#define DECD 512
#define EE   256
#define VV   5000
#define TT   96
#define GG   2048
#define VPAD 5120   // VV padded to multiple of 128

// ---------------- device scratch ----------------
__device__ __half g_att1[(size_t)BB * PP * DECD];     // 67 MB fp16
__device__ __half g_encb[(size_t)BB * PP * ENCD];     // 33.5 MB fp16
__device__ float  g_embW[(size_t)VV * GG];            // 41 MB fp32: emb @ wih_top
__device__ __half g_emb16[(size_t)VV * EE];
__device__ __half g_hall[(size_t)BB * TT * DECD];     // fp16 h history for batched fc
__device__ __half g_xh[BB * (ENCD + DECD)];           // per-step A: [xg | h] fp16, ld=768
__device__ float  g_h[BB * DECD];                     // h0 fp32 (init only)
__device__ float  g_c[2 * BB * DECD];
__device__ float  g_ag[BB * 768];                     // [att2 | gate] fp32
__device__ float  g_gates[BB * GG];
__device__ __half g_mean16[BB * ENCD];
__device__ float  g_bag[768];                         // concat bias dec_att_b|f_beta_b
// fp16 weights
__device__ __half g_wag[512 * 768];                   // [dec_att_w | f_beta_w]
__device__ __half g_wg[768 * GG];                     // [wih_bot ; whh]
__device__ __half g_wtop[256 * GG];                   // wih rows 0..255
__device__ __half g_wfc[512 * VPAD];                  // fc_w padded
__device__ __half g_wenc[256 * 512];                  // enc_att_w
__device__ __half g_wih0[256 * 512];
__device__ __half g_wic0[256 * 512];

__device__ __forceinline__ float sigmoidf(float x) { return 1.f / (1.f + expf(-x)); }

// ================= fp16 tensor-core GEMM =================
// C[M,N] = A[M,K](fp16,lda) @ W[K,N](fp16,ldw) + epilogue(MODE)
// block tile 128x128, 8 warps (2x4), warp tile 64x32, mma m16n8k16
__device__ __forceinline__ uint32_t smem_u32(const void* p) {
    return (uint32_t)__cvta_generic_to_shared(p);
}
__device__ __forceinline__ void ldm_x4(uint32_t* r, uint32_t addr) {
    asm volatile("ldmatrix.sync.aligned.m8n8.x4.shared.b16 {%0,%1,%2,%3}, [%4];"
                 : "=r"(r[0]), "=r"(r[1]), "=r"(r[2]), "=r"(r[3]) : "r"(addr));
}
__device__ __forceinline__ void ldm_x4_t(uint32_t* r, uint32_t addr) {
    asm volatile("ldmatrix.sync.aligned.m8n8.x4.trans.shared.b16 {%0,%1,%2,%3}, [%4];"
                 : "=r"(r[0]), "=r"(r[1]), "=r"(r[2]), "=r"(r[3]) : "r"(addr));
}
__device__ __forceinline__ void mma16816(float* c, const uint32_t* a, const uint32_t* b) {
    asm volatile("mma.sync.aligned.m16n8k16.row.col.f32.f16.f16.f32 "
                 "{%0,%1,%2,%3},{%4,%5,%6,%7},{%8,%9},{%0,%1,%2,%3};"
                 : "+f"(c[0]), "+f"(c[1]), "+f"(c[2]), "+f"(c[3])
                 : "r"(a[0]), "r"(a[1]), "r"(a[2]), "r"(a[3]), "r"(b[0]), "r"(b[1]));
}

// MODE: 0 plain fp32(+bias) | 1 att2gate (sigmoid n>=512) | 2 gates (+bias2+embW row)
//       3 fc (masked store, n<N guard) | 4 fp16 out (+bias)
template<int MODE>
__global__ __launch_bounds__(256, 1)
void hgemm_k(const __half* __restrict__ A, int lda,
             const __half* __restrict__ W, int ldw,
             const float* __restrict__ bias, const float* __restrict__ bias2,
             float* __restrict__ Cf, __half* __restrict__ Ch, int ldc,
             int M, int N, int K,
             const int* __restrict__ caps, const int* __restrict__ lens,
             const float* __restrict__ embW, int t)
{
    __shared__ __half As[128 * 64];
    __shared__ __half Bs[64 * 128];
    const int tid = threadIdx.x;
    const int warp = tid >> 5, lane = tid & 31;
    const int wm = (warp & 1) * 64, wn = (warp >> 1) * 32;
    const int m0 = blockIdx.y * 128, n0 = blockIdx.x * 128;

    float acc[4][4][4];
#pragma unroll
    for (int i = 0; i < 4; i++)
#pragma unroll
        for (int j = 0; j < 4; j++)
#pragma unroll
            for (int k = 0; k < 4; k++) acc[i][j][k] = 0.f;

    for (int kc = 0; kc < K; kc += 64) {
#pragma unroll
        for (int i = 0; i < 4; i++) {                 // A: 128 rows x 8 chunks(16B)
            int idx = tid + i * 256;
            int r = idx >> 3, c = idx & 7;
            int gm = m0 + r;
            float4 v = make_float4(0.f, 0.f, 0.f, 0.f);
            if (gm < M) v = *(const float4*)(A + (size_t)gm * lda + kc + c * 8);
            *(float4*)(As + r * 64 + (((c ^ r) & 7) << 3)) = v;
        }
#pragma unroll
        for (int i = 0; i < 4; i++) {                 // B: 64 rows x 16 chunks
            int idx = tid + i * 256;
            int r = idx >> 4, c = idx & 15;
            float4 v = *(const float4*)(W + (size_t)(kc + r) * ldw + n0 + c * 8);
            int sw = (c & 8) | ((c ^ r) & 7);
            *(float4*)(Bs + r * 128 + (sw << 3)) = v;
        }
        __syncthreads();
#pragma unroll
        for (int ks = 0; ks < 4; ks++) {
            uint32_t a[4][4], b[2][4];
#pragma unroll
            for (int mi = 0; mi < 4; mi++) {
                int m = wm + mi * 16 + (lane & 15);
                int kch = ks * 2 + (lane >> 4);
                ldm_x4(a[mi], smem_u32(As + m * 64 + (((kch ^ m) & 7) << 3)));
            }
#pragma unroll
            for (int ni = 0; ni < 2; ni++) {
                int k = ks * 16 + (lane & 15);
                int nch = (wn >> 3) + ni * 2 + (lane >> 4);
                int sw = (nch & 8) | ((nch ^ k) & 7);
                ldm_x4_t(b[ni], smem_u32(Bs + k * 128 + (sw << 3)));
            }
#pragma unroll
            for (int mi = 0; mi < 4; mi++)
#pragma unroll
                for (int ni = 0; ni < 4; ni++)
                    mma16816(acc[mi][ni], a[mi], &b[ni >> 1][(ni & 1) * 2]);
        }
        __syncthreads();
    }

    // epilogue
#pragma unroll
    for (int mi = 0; mi < 4; mi++) {
#pragma unroll
        for (int hh = 0; hh < 2; hh++) {
            int m = m0 + wm + mi * 16 + (lane >> 2) + hh * 8;
            if (m >= M) continue;
            int eidx = 0, active = 1, bfc = 0, tfc = 0;
            if (MODE == 2) eidx = caps[m * TT + t];
            if (MODE == 3) { bfc = m / TT; tfc = m - bfc * TT; active = (lens[bfc] > tfc); }
#pragma unroll
            for (int ni = 0; ni < 4; ni++) {
                int col = n0 + wn + ni * 8 + (lane & 3) * 2;
#pragma unroll
                for (int j = 0; j < 2; j++) {
                    int n = col + j;
                    float v = acc[mi][ni][hh * 2 + j];
                    if (bias) v += bias[n];
                    if (MODE == 0) {
                        Cf[(size_t)m * ldc + n] = v;
                    } else if (MODE == 1) {
                        if (n >= 512) v = sigmoidf(v);
                        Cf[(size_t)m * ldc + n] = v;
                    } else if (MODE == 2) {
                        v += bias2[n] + embW[(size_t)eidx * GG + n];
                        Cf[(size_t)m * ldc + n] = v;
                    } else if (MODE == 3) {
                        if (active && n < N) Cf[(size_t)m * ldc + n] = v;
                    } else { // 4
                        Ch[(size_t)m * ldc + n] = __float2half(v);
                    }
                }
            }
        }
    }
}

// ================= small kernels =================
__global__ void cvt_k(const float* __restrict__ src, __half* __restrict__ dst,
                      int rows, int cols, int sld, int dld, int valid)
{
    int n = rows * cols;
    for (int i = blockIdx.x * blockDim.x + threadIdx.x; i < n; i += gridDim.x * blockDim.x) {
        int r = i / cols, c = i - r * cols;
        float v = (c < valid) ? src[(size_t)r * sld + c] : 0.f;
        dst[(size_t)r * dld + c] = __float2half(v);
    }
}

__global__ void mean_k(const float* __restrict__ enc)
{
    int b = blockIdx.x, e = threadIdx.x;
    const float* p = enc + (size_t)b * PP * ENCD + e;
    float s = 0.f;
#pragma unroll 8
    for (int pp = 0; pp < PP; pp++) s += p[(size_t)pp * ENCD];
    g_mean16[b * ENCD + e] = __float2half(s * (1.f / PP));
}

__global__ void bag_k(const float* __restrict__ b1, const float* __restrict__ b2)
{
    int i = threadIdx.x + blockIdx.x * blockDim.x;
    if (i < 512) g_bag[i] = b1[i];
    else if (i < 768) g_bag[i] = b2[i - 512];
}

__global__ void h0c_k()
{
    int b = blockIdx.x, d = threadIdx.x;
    g_xh[b * 768 + 256 + d] = __float2half(g_h[b * DECD + d]);
}

__global__ void lens_k(const int* __restrict__ lens, float* __restrict__ o)
{
    o[threadIdx.x] = (float)lens[threadIdx.x];
}

// fused attention: e -> softmax -> awe -> xg(fp16)
__global__ __launch_bounds__(256)
void attention_k(const float* __restrict__ wfull, const int* __restrict__ lens,
                 int t, float* __restrict__ alphas_out)
{
    __shared__ float att2s[DECD];
    __shared__ float wf[DECD];
    __shared__ float es[PP];
    __shared__ float red[32];
    int b = blockIdx.x, tid = threadIdx.x;
    att2s[tid]       = g_ag[b * 768 + tid];
    att2s[tid + 256] = g_ag[b * 768 + 256 + tid];
    wf[tid]       = wfull[tid];
    wf[tid + 256] = wfull[tid + 256];
    __syncthreads();

    int warp = tid >> 5, lane = tid & 31;
    const __half2* a1 = reinterpret_cast<const __half2*>(g_att1 + (size_t)b * PP * DECD);
    for (int p = warp; p < PP; p += 8) {
        const __half2* row = a1 + (size_t)p * (DECD / 2);
        float acc = 0.f;
#pragma unroll
        for (int i = 0; i < DECD / 64; i++) {
            int d2 = lane + 32 * i;
            float2 v = __half22float2(row[d2]);
            float x0 = v.x + att2s[2 * d2];
            float x1 = v.y + att2s[2 * d2 + 1];
            acc += fmaxf(x0, 0.f) * wf[2 * d2] + fmaxf(x1, 0.f) * wf[2 * d2 + 1];
        }
#pragma unroll
        for (int o = 16; o > 0; o >>= 1) acc += __shfl_xor_sync(0xffffffffu, acc, o);
        if (lane == 0) es[p] = acc;
    }
    __syncthreads();

    float e = es[tid];
    float m = e;
#pragma unroll
    for (int o = 16; o > 0; o >>= 1) m = fmaxf(m, __shfl_xor_sync(0xffffffffu, m, o));
    if (lane == 0) red[warp] = m;
    __syncthreads();
    if (tid == 0) {
        float mm = red[0];
        for (int w = 1; w < 8; w++) mm = fmaxf(mm, red[w]);
        red[16] = mm;
    }
    __syncthreads();
    float ex = expf(e - red[16]);
    float s = ex;
#pragma unroll
    for (int o = 16; o > 0; o >>= 1) s += __shfl_xor_sync(0xffffffffu, s, o);
    if (lane == 0) red[warp] = s;
    __syncthreads();
    if (tid == 0) {
        float ss = 0.f;
        for (int w = 0; w < 8; w++) ss += red[w];
        red[17] = ss;
    }
    __syncthreads();
    float alpha = ex / red[17];
    es[tid] = alpha;
    int active = lens[b] > t;
    alphas_out[((size_t)b * TT + t) * PP + tid] = active ? alpha : 0.f;
    __syncthreads();

    const __half* eb = g_encb + (size_t)b * PP * ENCD;
    float acc = 0.f;
#pragma unroll 8
    for (int p = 0; p < PP; p++) acc += es[p] * __half2float(eb[(size_t)p * ENCD + tid]);
    float gate = g_ag[b * 768 + 512 + tid];
    g_xh[b * 768 + tid] = __float2half(gate * acc);
}

// LSTM cell pointwise; writes h fp16 to g_xh (recurrence) and g_hall (fc batch)
__global__ void cell_k(const float* __restrict__ cold, float* __restrict__ cnew, int t)
{
    int b = blockIdx.x, d = threadIdx.x;
    const float* g = g_gates + (size_t)b * GG;
    float ig = sigmoidf(g[d]);
    float fg = sigmoidf(g[DECD + d]);
    float gg = tanhf(g[2 * DECD + d]);
    float og = sigmoidf(g[3 * DECD + d]);
    float c = fg * cold[b * DECD + d] + ig * gg;
    cnew[b * DECD + d] = c;
    __half hh = __float2half(og * tanhf(c));
    g_xh[b * 768 + 256 + d] = hh;
    g_hall[((size_t)b * TT + t) * DECD + d] = hh;
}

// ================= host orchestration =================
static inline int cgrid(int n) { int g = (n + 255) / 256; return g > 4096 ? 4096 : g; }

extern "C" void kernel_launch(void* const* d_in, const int* in_sizes, int n_in,
                              void* d_out, int out_size)
{
    const float* enc        = (const float*)d_in[0];
    const int*   caps       = (const int*)d_in[1];
    const int*   lens       = (const int*)d_in[2];
    const float* embedding  = (const float*)d_in[3];
    const float* enc_att_w  = (const float*)d_in[4];
    const float* enc_att_b  = (const float*)d_in[5];
    const float* dec_att_w  = (const float*)d_in[6];
    const float* dec_att_b  = (const float*)d_in[7];
    const float* full_att_w = (const float*)d_in[8];
    const float* lstm_wih   = (const float*)d_in[10];
    const float* lstm_whh   = (const float*)d_in[11];
    const float* lstm_bih   = (const float*)d_in[12];
    const float* lstm_bhh   = (const float*)d_in[13];
    const float* init_h_w   = (const float*)d_in[14];
    const float* init_h_b   = (const float*)d_in[15];
    const float* init_c_w   = (const float*)d_in[16];
    const float* init_c_b   = (const float*)d_in[17];
    const float* f_beta_w   = (const float*)d_in[18];
    const float* f_beta_b   = (const float*)d_in[19];
    const float* fc_w       = (const float*)d_in[20];
    const float* fc_b       = (const float*)d_in[21];

    float* out      = (float*)d_out;
    float* out_pred = out;
    float* out_lens = out + (size_t)BB * TT * VV;
    float* out_alph = out_lens + BB;

    cudaMemsetAsync(d_out, 0, (size_t)out_size * sizeof(float));

    __half *p_encb, *p_emb16, *p_xh, *p_hall, *p_mean16, *p_att1;
    __half *p_wag, *p_wg, *p_wtop, *p_wfc, *p_wenc, *p_wih0, *p_wic0;
    float *p_h, *p_c, *p_ag, *p_gates, *p_embW, *p_bag;
    cudaGetSymbolAddress((void**)&p_encb, g_encb);
    cudaGetSymbolAddress((void**)&p_emb16, g_emb16);
    cudaGetSymbolAddress((void**)&p_xh, g_xh);
    cudaGetSymbolAddress((void**)&p_hall, g_hall);
    cudaGetSymbolAddress((void**)&p_mean16, g_mean16);
    cudaGetSymbolAddress((void**)&p_att1, g_att1);
    cudaGetSymbolAddress((void**)&p_wag, g_wag);
    cudaGetSymbolAddress((void**)&p_wg, g_wg);
    cudaGetSymbolAddress((void**)&p_wtop, g_wtop);
    cudaGetSymbolAddress((void**)&p_wfc, g_wfc);
    cudaGetSymbolAddress((void**)&p_wenc, g_wenc);
    cudaGetSymbolAddress((void**)&p_wih0, g_wih0);
    cudaGetSymbolAddress((void**)&p_wic0, g_wic0);
    cudaGetSymbolAddress((void**)&p_h, g_h);
    cudaGetSymbolAddress((void**)&p_c, g_c);
    cudaGetSymbolAddress((void**)&p_ag, g_ag);
    cudaGetSymbolAddress((void**)&p_gates, g_gates);
    cudaGetSymbolAddress((void**)&p_embW, g_embW);
    cudaGetSymbolAddress((void**)&p_bag, g_bag);

    // ---- weight conversions (fp32 -> fp16) ----
    cvt_k<<<cgrid(BB * PP * ENCD), 256>>>(enc, p_encb, BB * PP, ENCD, ENCD, ENCD, ENCD);
    cvt_k<<<cgrid(VV * EE), 256>>>(embedding, p_emb16, VV, EE, EE, EE, EE);
    cvt_k<<<cgrid(512 * 512), 256>>>(dec_att_w, p_wag, 512, 512, 512, 768, 512);
    cvt_k<<<cgrid(512 * 256), 256>>>(f_beta_w, p_wag + 512, 512, 256, 256, 768, 256);
    cvt_k<<<cgrid(256 * GG), 256>>>(lstm_wih, p_wtop, 256, GG, GG, GG, GG);
    cvt_k<<<cgrid(256 * GG), 256>>>(lstm_wih + (size_t)EE * GG, p_wg, 256, GG, GG, GG, GG);
    cvt_k<<<cgrid(512 * GG), 256>>>(lstm_whh, p_wg + (size_t)256 * GG, 512, GG, GG, GG, GG);
    cvt_k<<<cgrid(512 * VPAD), 256>>>(fc_w, p_wfc, 512, VPAD, VV, VPAD, VV);
    cvt_k<<<cgrid(256 * 512), 256>>>(enc_att_w, p_wenc, 256, 512, 512, 512, 512);
    cvt_k<<<cgrid(256 * 512), 256>>>(init_h_w, p_wih0, 256, 512, 512, 512, 512);
    cvt_k<<<cgrid(256 * 512), 256>>>(init_c_w, p_wic0, 256, 512, 512, 512, 512);
    bag_k<<<3, 256>>>(dec_att_b, f_beta_b);
    mean_k<<<BB, 256>>>(enc);

    // ---- one-time TC GEMMs ----
    // h0, c0
    hgemm_k<0><<<dim3(DECD / 128, BB / 128), 256>>>(p_mean16, ENCD, p_wih0, DECD,
        init_h_b, nullptr, p_h, nullptr, DECD, BB, DECD, ENCD, nullptr, nullptr, nullptr, 0);
    hgemm_k<0><<<dim3(DECD / 128, BB / 128), 256>>>(p_mean16, ENCD, p_wic0, DECD,
        init_c_b, nullptr, p_c, nullptr, DECD, BB, DECD, ENCD, nullptr, nullptr, nullptr, 0);
    h0c_k<<<BB, DECD>>>();
    // att1 = enc @ enc_att_w + b  (fp16 out)
    hgemm_k<4><<<dim3(DECD / 128, (BB * PP) / 128), 256>>>(p_encb, ENCD, p_wenc, DECD,
        enc_att_b, nullptr, nullptr, p_att1, DECD, BB * PP, DECD, ENCD, nullptr, nullptr, nullptr, 0);
    // embW = embedding @ wih_top
    hgemm_k<0><<<dim3(GG / 128, (VV + 127) / 128), 256>>>(p_emb16, EE, p_wtop, GG,
        nullptr, nullptr, p_embW, nullptr, GG, VV, GG, EE, nullptr, nullptr, nullptr, 0);

    // ---- timestep loop ----
    for (int t = 0; t < TT; t++) {
        const float* ccur = p_c + (t & 1) * (BB * DECD);
        float*       cnext = p_c + ((t + 1) & 1) * (BB * DECD);

        // [att2 | gate] = h @ [dec_att_w | f_beta_w] + bag, sigmoid on cols>=512
        hgemm_k<1><<<dim3(768 / 128, BB / 128), 256>>>(p_xh + 256, 768, p_wag, 768,
            p_bag, nullptr, p_ag, nullptr, 768, BB, 768, DECD, nullptr, nullptr, nullptr, 0);
        attention_k<<<BB, 256>>>(full_att_w, lens, t, out_alph);
        // gates = [xg|h] @ [wih_bot;whh] + bih + bhh + embW[cap]
        hgemm_k<2><<<dim3(GG / 128, BB / 128), 256>>>(p_xh, 768, p_wg, GG,
            lstm_bih, lstm_bhh, p_gates, nullptr, GG, BB, GG, 768, caps, nullptr, p_embW, t);
        cell_k<<<BB, DECD>>>(ccur, cnext, t);
    }

    // ---- batched fc over all (b,t), masked by lens ----
    hgemm_k<3><<<dim3(VPAD / 128, (BB * TT) / 128), 256>>>(p_hall, DECD, p_wfc, VPAD,
        fc_b, nullptr, out_pred, nullptr, VV, BB * TT, VV, DECD, nullptr, lens, nullptr, 0);

    lens_k<<<1, BB>>>(lens, out_lens);
}

// round 5
// speedup vs baseline: 2.5688x; 1.1614x over previous
#include <cuda_runtime.h>
#include <cuda_fp16.h>
#include <cstddef>
#include <cstdint>

#define BB   256
#define PP   256
#define ENCD 256
#define DECD 512
#define EE   256
#define VV   5000
#define TT   96
#define GG   2048
#define VPAD 5120

#define SMEMSZ 65536   // 2-stage: 2*(128*64 + 64*128) halves = 64 KB

// ---------------- device scratch ----------------
__device__ __half g_att1[(size_t)BB * PP * DECD];
__device__ __half g_encb[(size_t)BB * PP * ENCD];
__device__ float  g_embW[(size_t)VV * GG];
__device__ __half g_emb16[(size_t)VV * EE];
__device__ __half g_hall[(size_t)BB * TT * DECD];   // t-major: [(t*BB+b)*DECD+d]
__device__ __half g_xh[BB * (ENCD + DECD)];
__device__ float  g_h[BB * DECD];
__device__ float  g_c[2 * BB * DECD];
__device__ float  g_ag[BB * 768];
__device__ float  g_gates[BB * GG];
__device__ __half g_mean16[BB * ENCD];
__device__ float  g_bag[768];
__device__ __half g_wag[512 * 768];
__device__ __half g_wg[768 * GG];
__device__ __half g_wtop[256 * GG];
__device__ __half g_wfc[512 * VPAD];
__device__ __half g_wenc[256 * 512];
__device__ __half g_wih0[256 * 512];
__device__ __half g_wic0[256 * 512];

__device__ __forceinline__ float sigmoidf(float x) { return 1.f / (1.f + expf(-x)); }

// ================= pipelined fp16 tensor-core GEMM =================
__device__ __forceinline__ uint32_t smem_u32(const void* p) {
    return (uint32_t)__cvta_generic_to_shared(p);
}
__device__ __forceinline__ void cp16(void* dst, const void* src) {
    asm volatile("cp.async.cg.shared.global [%0], [%1], 16;"
                 :: "r"(smem_u32(dst)), "l"(src));
}
__device__ __forceinline__ void cp_commit() { asm volatile("cp.async.commit_group;"); }
template<int N>
__device__ __forceinline__ void cp_wait() { asm volatile("cp.async.wait_group %0;" :: "n"(N)); }

__device__ __forceinline__ void ldm_x4(uint32_t* r, uint32_t addr) {
    asm volatile("ldmatrix.sync.aligned.m8n8.x4.shared.b16 {%0,%1,%2,%3}, [%4];"
                 : "=r"(r[0]), "=r"(r[1]), "=r"(r[2]), "=r"(r[3]) : "r"(addr));
}
__device__ __forceinline__ void ldm_x4_t(uint32_t* r, uint32_t addr) {
    asm volatile("ldmatrix.sync.aligned.m8n8.x4.trans.shared.b16 {%0,%1,%2,%3}, [%4];"
                 : "=r"(r[0]), "=r"(r[1]), "=r"(r[2]), "=r"(r[3]) : "r"(addr));
}
__device__ __forceinline__ void mma16816(float* c, const uint32_t* a, const uint32_t* b) {
    asm volatile("mma.sync.aligned.m16n8k16.row.col.f32.f16.f16.f32 "
                 "{%0,%1,%2,%3},{%4,%5,%6,%7},{%8,%9},{%0,%1,%2,%3};"
                 : "+f"(c[0]), "+f"(c[1]), "+f"(c[2]), "+f"(c[3])
                 : "r"(a[0]), "r"(a[1]), "r"(a[2]), "r"(a[3]), "r"(b[0]), "r"(b[1]));
}

// MODE: 0 fp32(+bias) | 1 att2gate (sigmoid n>=512) | 2 gates (+bias2+embW[cap])
//       3 fc t-major (tile skip, masked, transposed store) | 4 fp16 out (+bias)
// For MODE 3, 't' carries the chunk row offset (mbase).
template<int MODE>
__global__ __launch_bounds__(256)
void hgemm_k(const __half* __restrict__ A, int lda,
             const __half* __restrict__ W, int ldw,
             const float* __restrict__ bias, const float* __restrict__ bias2,
             float* __restrict__ Cf, __half* __restrict__ Ch, int ldc,
             int M, int N, int K,
             const int* __restrict__ caps, const int* __restrict__ lens,
             const float* __restrict__ embW, int t)
{
    extern __shared__ __half sm[];
    __half* As = sm;            // 2 stages * 8192 halves
    __half* Bs = sm + 16384;    // 2 stages * 8192 halves
    const int tid = threadIdx.x;
    const int warp = tid >> 5, lane = tid & 31;
    const int wm = (warp & 1) * 64, wn = (warp >> 1) * 32;
    const int m0 = blockIdx.y * 128 + (MODE == 3 ? t : 0);
    const int n0 = blockIdx.x * 128;

    if (MODE == 3) {
        int tt = m0 >> 8, bmin = m0 & 255;
        if (lens[bmin] <= tt) return;   // whole tile inactive (lens sorted desc)
    }

    float acc[4][4][4];
#pragma unroll
    for (int i = 0; i < 4; i++)
#pragma unroll
        for (int j = 0; j < 4; j++)
#pragma unroll
            for (int k = 0; k < 4; k++) acc[i][j][k] = 0.f;

    const int nk = K >> 6;

    // ---- async load helpers (inline) ----
#define LOAD_A(stage, kc)                                                        \
    {                                                                            \
        _Pragma("unroll")                                                        \
        for (int i = 0; i < 4; i++) {                                            \
            int idx = tid + i * 256;                                             \
            int r = idx >> 3, c = idx & 7;                                       \
            int gm = m0 + r; if (gm >= M) gm = M - 1;                            \
            cp16(As + (stage) * 8192 + r * 64 + (((c ^ r) & 7) << 3),            \
                 A + (size_t)gm * lda + (kc) + c * 8);                           \
        }                                                                        \
    }
#define LOAD_B(stage, kc)                                                        \
    {                                                                            \
        _Pragma("unroll")                                                        \
        for (int i = 0; i < 4; i++) {                                            \
            int idx = tid + i * 256;                                             \
            int r = idx >> 4, c = idx & 15;                                      \
            int sw = (c & 8) | ((c ^ r) & 7);                                    \
            cp16(Bs + (stage) * 8192 + r * 128 + (sw << 3),                      \
                 W + (size_t)((kc) + r) * ldw + n0 + c * 8);                     \
        }                                                                        \
    }

    LOAD_A(0, 0); LOAD_B(0, 0); cp_commit();

    for (int k = 0; k < nk; k++) {
        int cur = k & 1;
        if (k + 1 < nk) {
            LOAD_A(cur ^ 1, (k + 1) * 64);
            LOAD_B(cur ^ 1, (k + 1) * 64);
            cp_commit();
            cp_wait<1>();
        } else {
            cp_wait<0>();
        }
        __syncthreads();

        const __half* Ab = As + cur * 8192;
        const __half* Bb = Bs + cur * 8192;
#pragma unroll
        for (int ks = 0; ks < 4; ks++) {
            uint32_t a[4][4], b[2][4];
#pragma unroll
            for (int mi = 0; mi < 4; mi++) {
                int m = wm + mi * 16 + (lane & 15);
                int kch = ks * 2 + (lane >> 4);
                ldm_x4(a[mi], smem_u32(Ab + m * 64 + (((kch ^ m) & 7) << 3)));
            }
#pragma unroll
            for (int ni = 0; ni < 2; ni++) {
                int kk = ks * 16 + (lane & 15);
                int nch = (wn >> 3) + ni * 2 + (lane >> 4);
                int sw = (nch & 8) | ((nch ^ kk) & 7);
                ldm_x4_t(b[ni], smem_u32(Bb + kk * 128 + (sw << 3)));
            }
#pragma unroll
            for (int mi = 0; mi < 4; mi++)
#pragma unroll
                for (int ni = 0; ni < 4; ni++)
                    mma16816(acc[mi][ni], a[mi], &b[ni >> 1][(ni & 1) * 2]);
        }
        __syncthreads();
    }
#undef LOAD_A
#undef LOAD_B

    // ---- epilogue ----
#pragma unroll
    for (int mi = 0; mi < 4; mi++) {
#pragma unroll
        for (int hh = 0; hh < 2; hh++) {
            int m = m0 + wm + mi * 16 + (lane >> 2) + hh * 8;
            if (m >= M) continue;
            int eidx = 0, active = 1, bo = 0, to = 0;
            if (MODE == 2) eidx = caps[m * TT + t];
            if (MODE == 3) {
                to = m >> 8; bo = m & 255;
                active = (lens[bo] > to);
            }
#pragma unroll
            for (int ni = 0; ni < 4; ni++) {
                int col = n0 + wn + ni * 8 + (lane & 3) * 2;
#pragma unroll
                for (int j = 0; j < 2; j++) {
                    int n = col + j;
                    float v = acc[mi][ni][hh * 2 + j];
                    if (bias) v += bias[n];
                    if (MODE == 0) {
                        Cf[(size_t)m * ldc + n] = v;
                    } else if (MODE == 1) {
                        if (n >= 512) v = sigmoidf(v);
                        Cf[(size_t)m * ldc + n] = v;
                    } else if (MODE == 2) {
                        v += bias2[n] + embW[(size_t)eidx * GG + n];
                        Cf[(size_t)m * ldc + n] = v;
                    } else if (MODE == 3) {
                        if (active && n < N)
                            Cf[((size_t)bo * TT + to) * ldc + n] = v;
                    } else {
                        Ch[(size_t)m * ldc + n] = __float2half(v);
                    }
                }
            }
        }
    }
}

// ================= small kernels =================
__global__ void cvt_k(const float* __restrict__ src, __half* __restrict__ dst,
                      int rows, int cols, int sld, int dld, int valid)
{
    int n = rows * cols;
    for (int i = blockIdx.x * blockDim.x + threadIdx.x; i < n; i += gridDim.x * blockDim.x) {
        int r = i / cols, c = i - r * cols;
        float v = (c < valid) ? src[(size_t)r * sld + c] : 0.f;
        dst[(size_t)r * dld + c] = __float2half(v);
    }
}

__global__ void mean_k(const float* __restrict__ enc)
{
    int b = blockIdx.x, e = threadIdx.x;
    const float* p = enc + (size_t)b * PP * ENCD + e;
    float s = 0.f;
#pragma unroll 8
    for (int pp = 0; pp < PP; pp++) s += p[(size_t)pp * ENCD];
    g_mean16[b * ENCD + e] = __float2half(s * (1.f / PP));
}

__global__ void bag_k(const float* __restrict__ b1, const float* __restrict__ b2)
{
    int i = threadIdx.x + blockIdx.x * blockDim.x;
    if (i < 512) g_bag[i] = b1[i];
    else if (i < 768) g_bag[i] = b2[i - 512];
}

__global__ void h0c_k()
{
    int b = blockIdx.x, d = threadIdx.x;
    g_xh[b * 768 + 256 + d] = __float2half(g_h[b * DECD + d]);
}

__global__ void lens_k(const int* __restrict__ lens, float* __restrict__ o)
{
    o[threadIdx.x] = (float)lens[threadIdx.x];
}

// fused attention: e -> softmax -> awe -> xg(fp16)
__global__ __launch_bounds__(256)
void attention_k(const float* __restrict__ wfull, const int* __restrict__ lens,
                 int t, float* __restrict__ alphas_out)
{
    __shared__ float att2s[DECD];
    __shared__ float wf[DECD];
    __shared__ float es[PP];
    __shared__ float red[32];
    int b = blockIdx.x, tid = threadIdx.x;
    att2s[tid]       = g_ag[b * 768 + tid];
    att2s[tid + 256] = g_ag[b * 768 + 256 + tid];
    wf[tid]       = wfull[tid];
    wf[tid + 256] = wfull[tid + 256];
    __syncthreads();

    int warp = tid >> 5, lane = tid & 31;
    const __half2* a1 = reinterpret_cast<const __half2*>(g_att1 + (size_t)b * PP * DECD);
    for (int p = warp; p < PP; p += 8) {
        const __half2* row = a1 + (size_t)p * (DECD / 2);
        float acc = 0.f;
#pragma unroll
        for (int i = 0; i < DECD / 64; i++) {
            int d2 = lane + 32 * i;
            float2 v = __half22float2(row[d2]);
            float x0 = v.x + att2s[2 * d2];
            float x1 = v.y + att2s[2 * d2 + 1];
            acc += fmaxf(x0, 0.f) * wf[2 * d2] + fmaxf(x1, 0.f) * wf[2 * d2 + 1];
        }
#pragma unroll
        for (int o = 16; o > 0; o >>= 1) acc += __shfl_xor_sync(0xffffffffu, acc, o);
        if (lane == 0) es[p] = acc;
    }
    __syncthreads();

    float e = es[tid];
    float m = e;
#pragma unroll
    for (int o = 16; o > 0; o >>= 1) m = fmaxf(m, __shfl_xor_sync(0xffffffffu, m, o));
    if (lane == 0) red[warp] = m;
    __syncthreads();
    if (tid == 0) {
        float mm = red[0];
        for (int w = 1; w < 8; w++) mm = fmaxf(mm, red[w]);
        red[16] = mm;
    }
    __syncthreads();
    float ex = expf(e - red[16]);
    float s = ex;
#pragma unroll
    for (int o = 16; o > 0; o >>= 1) s += __shfl_xor_sync(0xffffffffu, s, o);
    if (lane == 0) red[warp] = s;
    __syncthreads();
    if (tid == 0) {
        float ss = 0.f;
        for (int w = 0; w < 8; w++) ss += red[w];
        red[17] = ss;
    }
    __syncthreads();
    float alpha = ex / red[17];
    es[tid] = alpha;
    int active = lens[b] > t;
    alphas_out[((size_t)b * TT + t) * PP + tid] = active ? alpha : 0.f;
    __syncthreads();

    const __half* eb = g_encb + (size_t)b * PP * ENCD;
    float acc = 0.f;
#pragma unroll 8
    for (int p = 0; p < PP; p++) acc += es[p] * __half2float(eb[(size_t)p * ENCD + tid]);
    float gate = g_ag[b * 768 + 512 + tid];
    g_xh[b * 768 + tid] = __float2half(gate * acc);
}

// LSTM cell; h fp16 -> g_xh (recurrence) and g_hall t-major (fc batch)
__global__ void cell_k(const float* __restrict__ cold, float* __restrict__ cnew, int t)
{
    int b = blockIdx.x, d = threadIdx.x;
    const float* g = g_gates + (size_t)b * GG;
    float ig = sigmoidf(g[d]);
    float fg = sigmoidf(g[DECD + d]);
    float gg = tanhf(g[2 * DECD + d]);
    float og = sigmoidf(g[3 * DECD + d]);
    float c = fg * cold[b * DECD + d] + ig * gg;
    cnew[b * DECD + d] = c;
    __half hh = __float2half(og * tanhf(c));
    g_xh[b * 768 + 256 + d] = hh;
    g_hall[((size_t)t * BB + b) * DECD + d] = hh;
}

// ================= host orchestration =================
static inline int cgrid(int n) { int g = (n + 255) / 256; return g > 4096 ? 4096 : g; }

extern "C" void kernel_launch(void* const* d_in, const int* in_sizes, int n_in,
                              void* d_out, int out_size)
{
    const float* enc        = (const float*)d_in[0];
    const int*   caps       = (const int*)d_in[1];
    const int*   lens       = (const int*)d_in[2];
    const float* embedding  = (const float*)d_in[3];
    const float* enc_att_w  = (const float*)d_in[4];
    const float* enc_att_b  = (const float*)d_in[5];
    const float* dec_att_w  = (const float*)d_in[6];
    const float* dec_att_b  = (const float*)d_in[7];
    const float* full_att_w = (const float*)d_in[8];
    const float* lstm_wih   = (const float*)d_in[10];
    const float* lstm_whh   = (const float*)d_in[11];
    const float* lstm_bih   = (const float*)d_in[12];
    const float* lstm_bhh   = (const float*)d_in[13];
    const float* init_h_w   = (const float*)d_in[14];
    const float* init_h_b   = (const float*)d_in[15];
    const float* init_c_w   = (const float*)d_in[16];
    const float* init_c_b   = (const float*)d_in[17];
    const float* f_beta_w   = (const float*)d_in[18];
    const float* f_beta_b   = (const float*)d_in[19];
    const float* fc_w       = (const float*)d_in[20];
    const float* fc_b       = (const float*)d_in[21];

    float* out      = (float*)d_out;
    float* out_pred = out;
    float* out_lens = out + (size_t)BB * TT * VV;
    float* out_alph = out_lens + BB;

    // raise dynamic smem limit for all instantiations (host-side, idempotent)
    cudaFuncSetAttribute(hgemm_k<0>, cudaFuncAttributeMaxDynamicSharedMemorySize, SMEMSZ);
    cudaFuncSetAttribute(hgemm_k<1>, cudaFuncAttributeMaxDynamicSharedMemorySize, SMEMSZ);
    cudaFuncSetAttribute(hgemm_k<2>, cudaFuncAttributeMaxDynamicSharedMemorySize, SMEMSZ);
    cudaFuncSetAttribute(hgemm_k<3>, cudaFuncAttributeMaxDynamicSharedMemorySize, SMEMSZ);
    cudaFuncSetAttribute(hgemm_k<4>, cudaFuncAttributeMaxDynamicSharedMemorySize, SMEMSZ);

    // second stream + events for fc overlap (leaked intentionally; few calls total)
    cudaStream_t s2;
    cudaStreamCreateWithFlags(&s2, cudaStreamNonBlocking);
    cudaEvent_t evA[TT / 8], evB[TT / 8];
    for (int i = 0; i < TT / 8; i++) {
        cudaEventCreateWithFlags(&evA[i], cudaEventDisableTiming);
        cudaEventCreateWithFlags(&evB[i], cudaEventDisableTiming);
    }

    cudaMemsetAsync(d_out, 0, (size_t)out_size * sizeof(float));

    __half *p_encb, *p_emb16, *p_xh, *p_hall, *p_mean16, *p_att1;
    __half *p_wag, *p_wg, *p_wtop, *p_wfc, *p_wenc, *p_wih0, *p_wic0;
    float *p_h, *p_c, *p_ag, *p_gates, *p_embW, *p_bag;
    cudaGetSymbolAddress((void**)&p_encb, g_encb);
    cudaGetSymbolAddress((void**)&p_emb16, g_emb16);
    cudaGetSymbolAddress((void**)&p_xh, g_xh);
    cudaGetSymbolAddress((void**)&p_hall, g_hall);
    cudaGetSymbolAddress((void**)&p_mean16, g_mean16);
    cudaGetSymbolAddress((void**)&p_att1, g_att1);
    cudaGetSymbolAddress((void**)&p_wag, g_wag);
    cudaGetSymbolAddress((void**)&p_wg, g_wg);
    cudaGetSymbolAddress((void**)&p_wtop, g_wtop);
    cudaGetSymbolAddress((void**)&p_wfc, g_wfc);
    cudaGetSymbolAddress((void**)&p_wenc, g_wenc);
    cudaGetSymbolAddress((void**)&p_wih0, g_wih0);
    cudaGetSymbolAddress((void**)&p_wic0, g_wic0);
    cudaGetSymbolAddress((void**)&p_h, g_h);
    cudaGetSymbolAddress((void**)&p_c, g_c);
    cudaGetSymbolAddress((void**)&p_ag, g_ag);
    cudaGetSymbolAddress((void**)&p_gates, g_gates);
    cudaGetSymbolAddress((void**)&p_embW, g_embW);
    cudaGetSymbolAddress((void**)&p_bag, g_bag);

    // ---- conversions (fp32 -> fp16) ----
    cvt_k<<<cgrid(BB * PP * ENCD), 256>>>(enc, p_encb, BB * PP, ENCD, ENCD, ENCD, ENCD);
    cvt_k<<<cgrid(VV * EE), 256>>>(embedding, p_emb16, VV, EE, EE, EE, EE);
    cvt_k<<<cgrid(512 * 512), 256>>>(dec_att_w, p_wag, 512, 512, 512, 768, 512);
    cvt_k<<<cgrid(512 * 256), 256>>>(f_beta_w, p_wag + 512, 512, 256, 256, 768, 256);
    cvt_k<<<cgrid(256 * GG), 256>>>(lstm_wih, p_wtop, 256, GG, GG, GG, GG);
    cvt_k<<<cgrid(256 * GG), 256>>>(lstm_wih + (size_t)EE * GG, p_wg, 256, GG, GG, GG, GG);
    cvt_k<<<cgrid(512 * GG), 256>>>(lstm_whh, p_wg + (size_t)256 * GG, 512, GG, GG, GG, GG);
    cvt_k<<<cgrid(512 * VPAD), 256>>>(fc_w, p_wfc, 512, VPAD, VV, VPAD, VV);
    cvt_k<<<cgrid(256 * 512), 256>>>(enc_att_w, p_wenc, 256, 512, 512, 512, 512);
    cvt_k<<<cgrid(256 * 512), 256>>>(init_h_w, p_wih0, 256, 512, 512, 512, 512);
    cvt_k<<<cgrid(256 * 512), 256>>>(init_c_w, p_wic0, 256, 512, 512, 512, 512);
    bag_k<<<3, 256>>>(dec_att_b, f_beta_b);
    mean_k<<<BB, 256>>>(enc);

    // ---- one-time TC GEMMs ----
    hgemm_k<0><<<dim3(DECD / 128, BB / 128), 256, SMEMSZ>>>(p_mean16, ENCD, p_wih0, DECD,
        init_h_b, nullptr, p_h, nullptr, DECD, BB, DECD, ENCD, nullptr, nullptr, nullptr, 0);
    hgemm_k<0><<<dim3(DECD / 128, BB / 128), 256, SMEMSZ>>>(p_mean16, ENCD, p_wic0, DECD,
        init_c_b, nullptr, p_c, nullptr, DECD, BB, DECD, ENCD, nullptr, nullptr, nullptr, 0);
    h0c_k<<<BB, DECD>>>();
    hgemm_k<4><<<dim3(DECD / 128, (BB * PP) / 128), 256, SMEMSZ>>>(p_encb, ENCD, p_wenc, DECD,
        enc_att_b, nullptr, nullptr, p_att1, DECD, BB * PP, DECD, ENCD, nullptr, nullptr, nullptr, 0);
    hgemm_k<0><<<dim3(GG / 128, (VV + 127) / 128), 256, SMEMSZ>>>(p_emb16, EE, p_wtop, GG,
        nullptr, nullptr, p_embW, nullptr, GG, VV, GG, EE, nullptr, nullptr, nullptr, 0);

    // ---- timestep loop; fc chunks forked to s2 every 8 steps ----
    for (int t = 0; t < TT; t++) {
        const float* ccur = p_c + (t & 1) * (BB * DECD);
        float*       cnext = p_c + ((t + 1) & 1) * (BB * DECD);

        hgemm_k<1><<<dim3(768 / 128, BB / 128), 256, SMEMSZ>>>(p_xh + 256, 768, p_wag, 768,
            p_bag, nullptr, p_ag, nullptr, 768, BB, 768, DECD, nullptr, nullptr, nullptr, 0);
        attention_k<<<BB, 256>>>(full_att_w, lens, t, out_alph);
        hgemm_k<2><<<dim3(GG / 128, BB / 128), 256, SMEMSZ>>>(p_xh, 768, p_wg, GG,
            lstm_bih, lstm_bhh, p_gates, nullptr, GG, BB, GG, 768, caps, nullptr, p_embW, t);
        cell_k<<<BB, DECD>>>(ccur, cnext, t);

        if ((t & 7) == 7) {
            int c = t >> 3;
            cudaEventRecord(evA[c], 0);
            cudaStreamWaitEvent(s2, evA[c], 0);
            // fc for t in [8c, 8c+8): rows m = t*BB + b, 16 m-tiles x 40 n-tiles
            hgemm_k<3><<<dim3(VPAD / 128, 16), 256, SMEMSZ, s2>>>(p_hall, DECD, p_wfc, VPAD,
                fc_b, nullptr, out_pred, nullptr, VV, BB * TT, VV, DECD,
                nullptr, lens, nullptr, c * 8 * BB);
            cudaEventRecord(evB[c], s2);
        }
    }

    // join fc chunks back to main stream
    for (int c = 0; c < TT / 8; c++) cudaStreamWaitEvent(0, evB[c], 0);

    lens_k<<<1, BB>>>(lens, out_lens);
}